// round 2
// baseline (speedup 1.0000x reference)
#include <cuda_runtime.h>
#include <cuda_bf16.h>

// DensityLoss: out[b,y,x] = loss[b,y,x] * (fg ? 10 : 1) / (H*W) / B
// fg = pixel covered by >=1 of N boxes (half-open [y1:y2, x1:x2)).
//
// Strategy: one CTA per (b, y) image row. Build a 1D difference array over x
// for the boxes active at this row, block prefix-sum -> coverage count,
// fuse with the float4 loss*weight*scale multiply. Memory-bound: 64 MB traffic.

#define B_DIM 8
#define H_DIM 1024
#define W_DIM 1024
#define N_BOX 64
#define THREADS 256

__global__ __launch_bounds__(THREADS)
void density_loss_kernel(const float* __restrict__ loss,
                         const int4* __restrict__ bboxes,   // [B, N] as int4 (x1,y1,x2,y2)
                         float* __restrict__ out)
{
    __shared__ __align__(16) int diff[W_DIM + 4];   // +pad: x2 can be W
    __shared__ int warp_off[8];

    const int t   = threadIdx.x;
    const int row = blockIdx.x;            // b*H + y
    const int b   = row >> 10;             // H = 1024
    const int y   = row & (H_DIM - 1);

    // Zero the difference array (4 per thread + tail).
    diff[t]        = 0;
    diff[t + 256]  = 0;
    diff[t + 512]  = 0;
    diff[t + 768]  = 0;
    if (t < 4) diff[W_DIM + t] = 0;
    __syncthreads();

    // Scatter +/-1 at box x-extents for boxes active at this row.
    if (t < N_BOX) {
        int4 bx = bboxes[b * N_BOX + t];
        int x1 = min(max(bx.x, 0), W_DIM);
        int y1 = min(max(bx.y, 0), H_DIM);
        int x2 = min(max(bx.z, 0), W_DIM);
        int y2 = min(max(bx.w, 0), H_DIM);
        if (y >= y1 && y < y2 && x1 < x2) {
            atomicAdd(&diff[x1],  1);
            atomicAdd(&diff[x2], -1);
        }
    }
    __syncthreads();

    // Block-wide inclusive prefix sum over 1024 ints, 4 per thread.
    int4 v = *reinterpret_cast<const int4*>(&diff[t << 2]);
    int s0 = v.x;
    int s1 = s0 + v.y;
    int s2 = s1 + v.z;
    int s3 = s2 + v.w;
    const int total = s3;

    const int lane = t & 31;
    const int wid  = t >> 5;

    // Warp inclusive scan of per-thread totals.
    int incl = total;
    #pragma unroll
    for (int d = 1; d < 32; d <<= 1) {
        int n = __shfl_up_sync(0xffffffffu, incl, d);
        if (lane >= d) incl += n;
    }
    if (lane == 31) warp_off[wid] = incl;
    __syncthreads();

    // Warp 0 scans the 8 warp totals (exclusive).
    if (t < 8) {
        int w  = warp_off[t];
        int wi = w;
        #pragma unroll
        for (int d = 1; d < 8; d <<= 1) {
            int n = __shfl_up_sync(0xffu, wi, d);
            if (t >= d) wi += n;
        }
        warp_off[t] = wi - w;   // exclusive offset for warp t
    }
    __syncthreads();

    const int excl = warp_off[wid] + (incl - total);
    const int c0 = excl + s0;
    const int c1 = excl + s1;
    const int c2 = excl + s2;
    const int c3 = excl + s3;

    // Fused weight * scale. 1/(B*H*W) = 2^-23 (exact).
    const float INV  = 1.0f / (float)(B_DIM * H_DIM * W_DIM);
    const float WFG  = 10.0f * INV;

    const size_t base = (size_t)row * W_DIM + ((size_t)t << 2);
    float4 l = *reinterpret_cast<const float4*>(loss + base);
    float4 o;
    o.x = l.x * (c0 > 0 ? WFG : INV);
    o.y = l.y * (c1 > 0 ? WFG : INV);
    o.z = l.z * (c2 > 0 ? WFG : INV);
    o.w = l.w * (c3 > 0 ? WFG : INV);
    *reinterpret_cast<float4*>(out + base) = o;
}

extern "C" void kernel_launch(void* const* d_in, const int* in_sizes, int n_in,
                              void* d_out, int out_size)
{
    const float* loss   = (const float*)d_in[0];
    // d_in[1] = pred_densities: unused by the reference computation.
    const int4*  bboxes = (const int4*)d_in[2];
    float*       out    = (float*)d_out;

    density_loss_kernel<<<B_DIM * H_DIM, THREADS>>>(loss, bboxes, out);
}

// round 3
// speedup vs baseline: 1.0043x; 1.0043x over previous
#include <cuda_runtime.h>
#include <cuda_bf16.h>

// DensityLoss: out[b,y,x] = loss[b,y,x] * (fg ? 10 : 1) / (H*W) / B
// fg = pixel covered by >=1 of N boxes (half-open [y1:y2, x1:x2)).
//
// One CTA per (b, y) row: 1D difference array + block prefix sum, fused with
// the weighted multiply. This revision prefetches the loss float4 + box int4
// at kernel entry (overlapping DRAM latency with the scan), uses 3 barriers
// instead of 4, replaces the warp-0 serial combine with a direct per-thread
// sum of warp totals, and zeroes smem with STS.128.

#define B_DIM 8
#define H_DIM 1024
#define W_DIM 1024
#define N_BOX 64
#define THREADS 256

__global__ __launch_bounds__(THREADS)
void density_loss_kernel(const float* __restrict__ loss,
                         const int4* __restrict__ bboxes,   // [B, N] as int4 (x1,y1,x2,y2)
                         float* __restrict__ out)
{
    __shared__ __align__(16) int diff[W_DIM + 4];   // +pad: x2 can be W
    __shared__ int warp_tot[8];

    const int t   = threadIdx.x;
    const int row = blockIdx.x;            // b*H + y
    const int b   = row >> 10;             // H = 1024
    const int y   = row & (H_DIM - 1);

    // ---- Prefetch global data FIRST: overlap DRAM latency with the scan ----
    const size_t base = (size_t)row * W_DIM + ((size_t)t << 2);
    const float4 l = *reinterpret_cast<const float4*>(loss + base);

    int4 bx = make_int4(0, 0, 0, 0);
    if (t < N_BOX) bx = bboxes[b * N_BOX + t];

    // ---- Zero the difference array: one STS.128 per thread (+ pad) ----
    *reinterpret_cast<int4*>(&diff[t << 2]) = make_int4(0, 0, 0, 0);
    if (t == 0) *reinterpret_cast<int4*>(&diff[W_DIM]) = make_int4(0, 0, 0, 0);
    __syncthreads();

    // ---- Scatter +/-1 at box x-extents for boxes active at this row ----
    if (t < N_BOX) {
        int x1 = min(max(bx.x, 0), W_DIM);
        int y1 = min(max(bx.y, 0), H_DIM);
        int x2 = min(max(bx.z, 0), W_DIM);
        int y2 = min(max(bx.w, 0), H_DIM);
        if (y >= y1 && y < y2 && x1 < x2) {
            atomicAdd(&diff[x1],  1);
            atomicAdd(&diff[x2], -1);
        }
    }
    __syncthreads();

    // ---- Block-wide inclusive prefix sum over 1024 ints, 4 per thread ----
    const int4 v = *reinterpret_cast<const int4*>(&diff[t << 2]);
    const int s0 = v.x;
    const int s1 = s0 + v.y;
    const int s2 = s1 + v.z;
    const int s3 = s2 + v.w;

    const int lane = t & 31;
    const int wid  = t >> 5;

    // Warp inclusive scan of per-thread totals.
    int incl = s3;
    #pragma unroll
    for (int d = 1; d < 32; d <<= 1) {
        int n = __shfl_up_sync(0xffffffffu, incl, d);
        if (lane >= d) incl += n;
    }
    if (lane == 31) warp_tot[wid] = incl;
    __syncthreads();

    // Exclusive offset: within-warp exclusive + direct sum of prior warp totals.
    int excl = incl - s3;
    #pragma unroll
    for (int w = 0; w < 7; w++) {
        if (w < wid) excl += warp_tot[w];
    }

    const int c0 = excl + s0;
    const int c1 = excl + s1;
    const int c2 = excl + s2;
    const int c3 = excl + s3;

    // Fused weight * scale. 1/(B*H*W) = 2^-23 (exact).
    const float INV = 1.0f / (float)(B_DIM * H_DIM * W_DIM);
    const float WFG = 10.0f * INV;

    float4 o;
    o.x = l.x * (c0 > 0 ? WFG : INV);
    o.y = l.y * (c1 > 0 ? WFG : INV);
    o.z = l.z * (c2 > 0 ? WFG : INV);
    o.w = l.w * (c3 > 0 ? WFG : INV);
    *reinterpret_cast<float4*>(out + base) = o;
}

extern "C" void kernel_launch(void* const* d_in, const int* in_sizes, int n_in,
                              void* d_out, int out_size)
{
    const float* loss   = (const float*)d_in[0];
    // d_in[1] = pred_densities: unused by the reference computation.
    const int4*  bboxes = (const int4*)d_in[2];
    float*       out    = (float*)d_out;

    density_loss_kernel<<<B_DIM * H_DIM, THREADS>>>(loss, bboxes, out);
}

// round 7
// speedup vs baseline: 1.1600x; 1.1550x over previous
#include <cuda_runtime.h>
#include <cuda_bf16.h>

// DensityLoss: out[b,y,x] = loss[b,y,x] * (fg ? 10 : 1) / (H*W*B),  1/(H*W*B)=2^-23 exact.
// fg = pixel covered by >=1 of 64 boxes (half-open [y1:y2, x1:x2)).
//
// Round 4 algorithm: coverage is a boolean OR, so skip the difference-array
// prefix sum entirely. One WARP per image row builds a 1024-bit coverage
// bitmap (32 smem words) directly from box x-extents: interior words are
// plain stores of 0xffffffff (same-value race, benign), partial end words
// use atomicOr. The same warp then expands bits into weights fused with the
// float4 multiply. Producer == consumer warp => __syncwarp only, zero CTA
// barriers, zero shfl scans. ~7 instr/pixel vs ~14 for the scan version.

#define B_DIM 8
#define H_DIM 1024
#define W_DIM 1024
#define N_BOX 64
#define THREADS 256
#define ROWS_PER_CTA 8   // one warp per row

__global__ __launch_bounds__(THREADS)
void density_loss_kernel(const float* __restrict__ loss,
                         const int4* __restrict__ bboxes,   // [B, N] as int4 (x1,y1,x2,y2)
                         float* __restrict__ out)
{
    __shared__ unsigned bm[ROWS_PER_CTA][W_DIM / 32];   // 8 x 32 words = 1 KB

    const int t    = threadIdx.x;
    const int lane = t & 31;
    const int r    = t >> 5;                    // warp id == row within CTA
    const int row  = (blockIdx.x << 3) + r;     // b*H + y
    const int b    = row >> 10;                 // H = 1024
    const int y    = row & (H_DIM - 1);

    // ---- Zero this row's bitmap (1 word per lane) ----
    bm[r][lane] = 0u;

    // ---- Each lane owns 2 boxes ----
    const int4* bb = bboxes + (b << 6);
    const int4 b0 = bb[lane];
    const int4 b1 = bb[lane + 32];
    __syncwarp();

    #pragma unroll
    for (int k = 0; k < 2; k++) {
        const int4 bx = k ? b1 : b0;
        const int x1 = min(max(bx.x, 0), W_DIM);
        const int y1 = min(max(bx.y, 0), H_DIM);
        const int x2 = min(max(bx.z, 0), W_DIM);
        const int y2 = min(max(bx.w, 0), H_DIM);
        if (y >= y1 && y < y2 && x1 < x2) {
            const int wA = x1 >> 5;
            const int wB = (x2 - 1) >> 5;
            const unsigned mA = 0xffffffffu << (x1 & 31);
            const unsigned mB = 0xffffffffu >> (31 - ((x2 - 1) & 31));
            if (wA == wB) {
                atomicOr(&bm[r][wA], mA & mB);
            } else {
                atomicOr(&bm[r][wA], mA);
                atomicOr(&bm[r][wB], mB);
                for (int w = wA + 1; w < wB; w++)
                    bm[r][w] = 0xffffffffu;     // same-value race: benign
            }
        }
    }
    __syncwarp();

    // ---- Expand bits -> weights, fused with the multiply ----
    const float INV = 1.0f / 8388608.0f;   // 2^-23, exact
    const float WFG = 10.0f * INV;
    const size_t rowbase = (size_t)row << 10;
    const int shift = (lane & 7) << 2;     // nibble position within word

    #pragma unroll
    for (int q = 0; q < 8; q++) {
        const int gx = (q << 7) + (lane << 2);          // lanes contiguous: coalesced
        const unsigned m   = bm[r][(q << 2) + (lane >> 3)];  // broadcast LDS
        const unsigned nib = m >> shift;

        const float4 l4 = *reinterpret_cast<const float4*>(loss + rowbase + gx);
        float4 o;
        o.x = l4.x * ((nib & 1u) ? WFG : INV);
        o.y = l4.y * ((nib & 2u) ? WFG : INV);
        o.z = l4.z * ((nib & 4u) ? WFG : INV);
        o.w = l4.w * ((nib & 8u) ? WFG : INV);
        *reinterpret_cast<float4*>(out + rowbase + gx) = o;
    }
}

extern "C" void kernel_launch(void* const* d_in, const int* in_sizes, int n_in,
                              void* d_out, int out_size)
{
    const float* loss   = (const float*)d_in[0];
    // d_in[1] = pred_densities: unused by the reference computation.
    const int4*  bboxes = (const int4*)d_in[2];
    float*       out    = (float*)d_out;

    density_loss_kernel<<<(B_DIM * H_DIM) / ROWS_PER_CTA, THREADS>>>(loss, bboxes, out);
}

// round 9
// speedup vs baseline: 1.1629x; 1.0025x over previous
#include <cuda_runtime.h>
#include <cuda_bf16.h>

// DensityLoss: out[b,y,x] = loss[b,y,x] * (fg ? 10 : 1) / (H*W*B),  1/(H*W*B)=2^-23 exact.
// fg = pixel covered by >=1 of 64 boxes (half-open [y1:y2, x1:x2)).
//
// One WARP per image row. Round-8 change: software-pipeline for MLP=8 —
// all 8 row LDG.128s are issued at kernel ENTRY (they don't depend on the
// bitmap), their DRAM latency overlaps the bitmap build, and the consume
// phase only does LDS -> weight -> FMUL -> STG. Raises per-warp outstanding
// loads from ~2 to 8 so the chip hits the LTS/DRAM throughput cap instead
// of being latency-bound at occ*MLP too low.

#define B_DIM 8
#define H_DIM 1024
#define W_DIM 1024
#define N_BOX 64
#define THREADS 256
#define ROWS_PER_CTA 8   // one warp per row

__global__ __launch_bounds__(THREADS)
void density_loss_kernel(const float* __restrict__ loss,
                         const int4* __restrict__ bboxes,   // [B, N] as int4 (x1,y1,x2,y2)
                         float* __restrict__ out)
{
    __shared__ unsigned bm[ROWS_PER_CTA][W_DIM / 32];   // 8 x 32 words = 1 KB

    const int t    = threadIdx.x;
    const int lane = t & 31;
    const int r    = t >> 5;                    // warp id == row within CTA
    const int row  = (blockIdx.x << 3) + r;     // b*H + y
    const int b    = row >> 10;                 // H = 1024
    const int y    = row & (H_DIM - 1);

    // ---- Phase 0: issue ALL global loads first (MLP = 8 + boxes) ----
    const size_t rowbase = (size_t)row << 10;
    const float4* lp = reinterpret_cast<const float4*>(loss + rowbase) + lane;

    float4 l[8];
    #pragma unroll
    for (int q = 0; q < 8; q++)
        l[q] = lp[q << 5];                      // gx = q*128 + lane*4, coalesced

    const int4* bb = bboxes + (b << 6);
    const int4 b0 = bb[lane];
    const int4 b1 = bb[lane + 32];

    // ---- Phase 1: build this row's 1024-bit coverage bitmap ----
    bm[r][lane] = 0u;
    __syncwarp();

    #pragma unroll
    for (int k = 0; k < 2; k++) {
        const int4 bx = k ? b1 : b0;
        const int x1 = min(max(bx.x, 0), W_DIM);
        const int y1 = min(max(bx.y, 0), H_DIM);
        const int x2 = min(max(bx.z, 0), W_DIM);
        const int y2 = min(max(bx.w, 0), H_DIM);
        if (y >= y1 && y < y2 && x1 < x2) {
            const int wA = x1 >> 5;
            const int wB = (x2 - 1) >> 5;
            const unsigned mA = 0xffffffffu << (x1 & 31);
            const unsigned mB = 0xffffffffu >> (31 - ((x2 - 1) & 31));
            if (wA == wB) {
                atomicOr(&bm[r][wA], mA & mB);
            } else {
                atomicOr(&bm[r][wA], mA);
                atomicOr(&bm[r][wB], mB);
                for (int w = wA + 1; w < wB; w++)
                    bm[r][w] = 0xffffffffu;     // same-value race: benign
            }
        }
    }
    __syncwarp();

    // ---- Phase 2: expand bits -> weights, multiply, store ----
    const float INV = 1.0f / 8388608.0f;   // 2^-23, exact
    const float WFG = 10.0f * INV;
    const int shift = (lane & 7) << 2;     // nibble position within word

    float4* op = reinterpret_cast<float4*>(out + rowbase) + lane;

    #pragma unroll
    for (int q = 0; q < 8; q++) {
        const unsigned nib = bm[r][(q << 2) + (lane >> 3)] >> shift;  // broadcast LDS
        float4 o;
        o.x = l[q].x * ((nib & 1u) ? WFG : INV);
        o.y = l[q].y * ((nib & 2u) ? WFG : INV);
        o.z = l[q].z * ((nib & 4u) ? WFG : INV);
        o.w = l[q].w * ((nib & 8u) ? WFG : INV);
        op[q << 5] = o;
    }
}

extern "C" void kernel_launch(void* const* d_in, const int* in_sizes, int n_in,
                              void* d_out, int out_size)
{
    const float* loss   = (const float*)d_in[0];
    // d_in[1] = pred_densities: unused by the reference computation.
    const int4*  bboxes = (const int4*)d_in[2];
    float*       out    = (float*)d_out;

    density_loss_kernel<<<(B_DIM * H_DIM) / ROWS_PER_CTA, THREADS>>>(loss, bboxes, out);
}